// round 13
// baseline (speedup 1.0000x reference)
#include <cuda_runtime.h>
#include <cuda_fp16.h>
#include <cstdint>
#include <math_constants.h>

// ---------------------------------------------------------------------------
// Device scratch (static: allocation-free)
// ---------------------------------------------------------------------------
__device__ __half g_a [65536 * 256];   // A pixel-major [m][c] = fp16(x)
__device__ __half g_bh[512 * 256];     // normalized proto fp16 [p][c]
__device__ float  g_pnf[512 * 256];    // normalized protos fp32 (for fixup)
__device__ int    g_fixlist[65536];
__device__ int    g_nfix;

__device__ __forceinline__ uint32_t smem_u32(const void* p) {
    uint32_t a;
    asm("{ .reg .u64 t; cvta.to.shared.u64 t, %1; cvt.u32.u64 %0, t; }"
        : "=r"(a) : "l"(p));
    return a;
}
__device__ __forceinline__ void cpa16(uint32_t dst, const void* src) {
    asm volatile("cp.async.cg.shared.global [%0], [%1], 16;"
                 :: "r"(dst), "l"(src));
}
#define LDSM_X4(r0,r1,r2,r3,addr) \
    asm volatile("ldmatrix.sync.aligned.m8n8.x4.shared.b16 {%0,%1,%2,%3}, [%4];" \
        : "=r"(r0),"=r"(r1),"=r"(r2),"=r"(r3) : "r"(addr))
#define MMA16816(d,a,b) \
    asm volatile("mma.sync.aligned.m16n8k16.row.col.f32.f16.f16.f32 " \
        "{%0,%1,%2,%3},{%4,%5,%6,%7},{%8,%9},{%0,%1,%2,%3};" \
        : "+f"(d[0]),"+f"(d[1]),"+f"(d[2]),"+f"(d[3]) \
        : "r"(a[0]),"r"(a[1]),"r"(a[2]),"r"(a[3]),"r"(b[0]),"r"(b[1]))

// fp16-GEMM absolute error < ~3.2e-4 std; 4e-3 threshold = ~12 sigma.
#define FIX_THRESH 4e-3f

// ---------------------------------------------------------------------------
// Prep 1: normalize protos -> fp16 + fp32 copies; reset fix counter
// ---------------------------------------------------------------------------
__global__ void proto_prep_kernel(const float* __restrict__ proto) {
    __shared__ float sred[8];
    const int p = blockIdx.x, c = threadIdx.x;
    float v = proto[(p << 8) + c];
    float ss = v * v;
    #pragma unroll
    for (int s = 16; s >= 1; s >>= 1) ss += __shfl_xor_sync(0xffffffffu, ss, s);
    if ((c & 31) == 0) sred[c >> 5] = ss;
    __syncthreads();
    float tot = 0.f;
    #pragma unroll
    for (int w = 0; w < 8; ++w) tot += sred[w];
    const float pn = v / fmaxf(sqrtf(tot), 1e-12f);
    g_pnf[(p << 8) + c] = pn;
    g_bh[(p << 8) + c] = __float2half(pn);
    if (p == 0 && c == 0) g_nfix = 0;
}

// ---------------------------------------------------------------------------
// Prep 2: transpose x [b][c][m] -> A [m][c] fp16, half2 stores.
// grid (4, 32, 64) = (64-ch tiles, 32-m tiles, batch), 256 threads.
// t row stride 66 (even) keeps &t[m][2*lane] 8B-aligned for float2 reads.
// ---------------------------------------------------------------------------
__global__ void xsplit_kernel(const float* __restrict__ x) {
    __shared__ float t[32][66];
    const int b = blockIdx.z, c0 = blockIdx.x << 6, m0 = blockIdx.y << 5;
    const int lane = threadIdx.x & 31, w = threadIdx.x >> 5;
    #pragma unroll
    for (int i = 0; i < 8; ++i) {
        int c = w + (i << 3);
        t[lane][c] = x[b * 262144 + (c0 + c) * 1024 + m0 + lane];
    }
    __syncthreads();
    __half2* ga2 = reinterpret_cast<__half2*>(g_a);
    #pragma unroll
    for (int j = 0; j < 4; ++j) {
        int m = w + (j << 3);
        float2 f = *reinterpret_cast<const float2*>(&t[m][lane << 1]);
        __half2 h = __halves2half2(__float2half(f.x), __float2half(f.y));
        ga2[((size_t)(b * 1024 + m0 + m) << 7) + (c0 >> 1) + lane] = h;
    }
}

// ---------------------------------------------------------------------------
// B slice loader (512 threads): 128 protos x 64 ch fp16 = 16KB into buf (t%3).
// ---------------------------------------------------------------------------
__device__ __forceinline__ void load_bslice(uint32_t Bsm, int t, int tid) {
    const int pc = t >> 2, kb = t & 3;
    const char* src0 = reinterpret_cast<const char*>(g_bh);
    const uint32_t dst = Bsm + (uint32_t)(t % 3) * 16384u;
    #pragma unroll
    for (int i = 0; i < 2; ++i) {
        int u = tid + (i << 9);          // 0..1023 16B units
        int r = u >> 3, c = u & 7;
        uint32_t o = (uint32_t)(r << 7) + (uint32_t)(c << 4);
        const char* src = src0 + (size_t)(pc * 128 + r) * 512 + kb * 128 + (c << 4);
        cpa16(dst + (o ^ ((o >> 3) & 0x70)), src);
    }
}

// ---------------------------------------------------------------------------
// Main: 256 blocks x 256 pixels, 512 threads (16 warps, 4m x 4n warp grid,
// 64x32 tile/warp). A (256x256 fp16, 128KB) staged once; 16 B slices (16KB)
// 3-stage pipelined. fp16 GEMM, fp32 acc, top-2 + fused gather epilogue.
// ---------------------------------------------------------------------------
__global__ __launch_bounds__(512, 1)
void protomatch_mma(const float* __restrict__ proto,
                    float* __restrict__ out, long long out_size)
{
    extern __shared__ char dsm[];
    const uint32_t dynb = smem_u32(dsm);
    const uint32_t base = (dynb + 1023u) & ~1023u;
    char* base_g = dsm + (base - dynb);
    const uint32_t Asm = base;            // 131072 bytes (4 chunks x 32KB)
    const uint32_t Bsm = base + 131072u;  // 49152 bytes (3 bufs x 16KB)

    const int tid = threadIdx.x, lane = tid & 31, wid = tid >> 5;
    const int warp_m = wid & 3, warp_n = wid >> 2;   // 4 x 4
    const int m0 = blockIdx.x << 8;      // 256 pixels per block
    const int b = m0 >> 10, n0 = m0 & 1023;

    // ---- stage A (256 rows x 256 fp16 = 128KB) + first two B slices ----
    const char* Ag = reinterpret_cast<const char*>(g_a);
    #pragma unroll
    for (int i = 0; i < 16; ++i) {
        int u = tid + (i << 9);          // 0..8191 16B units
        int s = u >> 11;                 // chunk 0..3 (2048 units each)
        int r = (u >> 3) & 255;          // row 0..255
        int c = u & 7;                   // 16B col 0..7
        uint32_t o = (uint32_t)(r << 7) + (uint32_t)(c << 4);
        cpa16(Asm + (s << 15) + (o ^ ((o >> 3) & 0x70)),
              Ag + (size_t)(m0 + r) * 512 + (s << 7) + (c << 4));
    }
    load_bslice(Bsm, 0, tid);
    asm volatile("cp.async.commit_group;");
    load_bslice(Bsm, 1, tid);
    asm volatile("cp.async.commit_group;");

    // per-lane ldmatrix address components: 4 m-tiles of 16 rows per warp
    uint32_t aoff[4], aswz[4];
    #pragma unroll
    for (int mt = 0; mt < 4; ++mt) {
        int rowA = warp_m * 64 + mt * 16 + (lane & 15);
        aoff[mt] = (uint32_t)rowA << 7;
        aswz[mt] = (uint32_t)(rowA & 7);
    }
    const uint32_t alc = (uint32_t)(lane >> 4);        // k-half select for A

    uint32_t boff[2], bswz[2];
    #pragma unroll
    for (int nt2 = 0; nt2 < 2; ++nt2) {
        int rowB = warp_n * 32 + nt2 * 16 + ((lane >> 4) << 3) + (lane & 7);
        boff[nt2] = (uint32_t)rowB << 7;
        bswz[nt2] = (uint32_t)(rowB & 7);
    }
    const uint32_t blc = (uint32_t)((lane >> 3) & 1);  // k-half select for B

    float acc[4][4][4];
    float t1v[8], t2v[8];
    int   t1i[8];
    #pragma unroll
    for (int s = 0; s < 8; ++s) { t1v[s] = -CUDART_INF_F; t2v[s] = -CUDART_INF_F; t1i[s] = 0; }

    for (int t = 0; t < 16; ++t) {
        const int pc = t >> 2, kb = t & 3;
        if (kb == 0) {
            #pragma unroll
            for (int i = 0; i < 4; ++i)
                #pragma unroll
                for (int j = 0; j < 4; ++j)
                    #pragma unroll
                    for (int q = 0; q < 4; ++q) acc[i][j][q] = 0.f;
        }
        // pipeline: wait(tile t ready) -> sync -> issue copy t+2 -> compute
        if (t < 15) asm volatile("cp.async.wait_group 1;");
        else        asm volatile("cp.async.wait_group 0;");
        __syncthreads();
        if (t + 2 < 16) {
            load_bslice(Bsm, t + 2, tid);
            asm volatile("cp.async.commit_group;");
        }

        const uint32_t Ab = Asm + ((uint32_t)kb << 15);
        const uint32_t Bb = Bsm + (uint32_t)(t % 3) * 16384u;

        #pragma unroll
        for (int k16 = 0; k16 < 4; ++k16) {
            uint32_t ra[4][4];
            #pragma unroll
            for (int mt = 0; mt < 4; ++mt) {
                uint32_t c16 = (uint32_t)(k16 << 1) + alc;
                LDSM_X4(ra[mt][0], ra[mt][1], ra[mt][2], ra[mt][3],
                        Ab + aoff[mt] + ((c16 ^ aswz[mt]) << 4));
            }
            #pragma unroll
            for (int nt2 = 0; nt2 < 2; ++nt2) {
                uint32_t c16 = (uint32_t)(k16 << 1) + blc;
                uint32_t rb[4];
                LDSM_X4(rb[0], rb[1], rb[2], rb[3],
                        Bb + boff[nt2] + ((c16 ^ bswz[nt2]) << 4));
                #pragma unroll
                for (int mt = 0; mt < 4; ++mt) {
                    MMA16816(acc[mt][2*nt2+0], ra[mt], (rb + 0));
                    MMA16816(acc[mt][2*nt2+1], ra[mt], (rb + 2));
                }
            }
        }

        if (kb == 3) {     // fold chunk pc into running top-2
            #pragma unroll
            for (int mt = 0; mt < 4; ++mt)
                #pragma unroll
                for (int rh = 0; rh < 2; ++rh) {
                    int sl = mt * 2 + rh;
                    #pragma unroll
                    for (int nt = 0; nt < 4; ++nt)
                        #pragma unroll
                        for (int e = 0; e < 2; ++e) {
                            float v = acc[mt][nt][rh * 2 + e];
                            int col = (pc << 7) + (warp_n << 5) + (nt << 3)
                                    + ((lane & 3) << 1) + e;
                            if (v > t1v[sl]) { t2v[sl] = t1v[sl]; t1v[sl] = v; t1i[sl] = col; }
                            else if (v > t2v[sl]) t2v[sl] = v;
                        }
                }
        }
    }
    __syncthreads();

    // ---- cross-lane/warp reduction via smem (reuse A region) ----
    float* sv1 = reinterpret_cast<float*>(base_g);            // [256][16]
    int*   si1 = reinterpret_cast<int*>(base_g + 16384);
    float* sv2 = reinterpret_cast<float*>(base_g + 32768);
    int*   sIdx = reinterpret_cast<int*>(base_g + 49152);     // [256]
    #pragma unroll
    for (int mt = 0; mt < 4; ++mt)
        #pragma unroll
        for (int rh = 0; rh < 2; ++rh) {
            int sl = mt * 2 + rh;
            int row = warp_m * 64 + mt * 16 + rh * 8 + (lane >> 2);
            int cand = (warp_n << 2) + (lane & 3);
            sv1[row * 16 + cand] = t1v[sl];
            si1[row * 16 + cand] = t1i[sl];
            sv2[row * 16 + cand] = t2v[sl];
        }
    __syncthreads();

    if (tid < 256) {
        float v1 = -CUDART_INF_F, v2 = -CUDART_INF_F;
        int i1 = 0x7fffffff;
        #pragma unroll
        for (int c = 0; c < 16; ++c) {
            float cv1 = sv1[tid * 16 + c], cv2 = sv2[tid * 16 + c];
            int   ci1 = si1[tid * 16 + c];
            if (cv1 > v1 || (cv1 == v1 && ci1 < i1)) {
                v2 = fmaxf(v1, cv2); v1 = cv1; i1 = ci1;
            } else {
                v2 = fmaxf(v2, cv1);
            }
        }
        const int m = m0 + tid;
        sIdx[tid] = i1;
        if (out_size > 16777216LL) out[16777216 + m] = (float)i1;
        if (v1 - v2 < FIX_THRESH) {
            int pos = atomicAdd(&g_nfix, 1);
            g_fixlist[pos] = m;
        }
    }
    __syncthreads();

    // ---- fused gather: recon[b,c,h,w] = proto[idx][c], coalesced ----
    const int n4 = tid & 63;   // float4 col within 256-pixel tile
    const int ph = tid >> 6;   // channel phase 0..7
    const float* r0 = proto + (sIdx[(n4 << 2) + 0] << 8);
    const float* r1 = proto + (sIdx[(n4 << 2) + 1] << 8);
    const float* r2 = proto + (sIdx[(n4 << 2) + 2] << 8);
    const float* r3 = proto + (sIdx[(n4 << 2) + 3] << 8);
    float4* Og = reinterpret_cast<float4*>(out) + (b * 65536 + (n0 >> 2) + n4);
    #pragma unroll 4
    for (int c = ph; c < 256; c += 8)
        Og[c * 256] = make_float4(r0[c], r1[c], r2[c], r3[c]);
}

// ---------------------------------------------------------------------------
// Fixup: exact fp32 argmax, ONE flagged pixel per block (grid-stride, 1024
// blocks -> ~7 blocks/SM so L2 latency is hidden); patches recon row.
// ---------------------------------------------------------------------------
__global__ __launch_bounds__(256)
void fixup_kernel(const float* __restrict__ x, const float* __restrict__ proto,
                  float* __restrict__ out, long long out_size)
{
    __shared__ __align__(16) float xs[260];
    __shared__ float rbv[8];
    __shared__ int   rbi[8];
    __shared__ int   sfi;
    const int tid = threadIdx.x, lane = tid & 31, wid = tid >> 5;
    const int nfix = g_nfix;

    for (int e = blockIdx.x; e < nfix; e += gridDim.x) {
        const int m = g_fixlist[e];
        xs[tid] = x[(m >> 10) * 262144 + tid * 1024 + (m & 1023)];
        __syncthreads();

        float bv = -CUDART_INF_F;
        int   bi = 0;
        #pragma unroll
        for (int h = 0; h < 2; ++h) {
            const int p = tid + (h << 8);
            const float4* pr = reinterpret_cast<const float4*>(g_pnf + (p << 8));
            const float4* xv4 = reinterpret_cast<const float4*>(xs);
            float a0 = 0.f, a1 = 0.f;
            #pragma unroll 8
            for (int c4 = 0; c4 < 64; c4 += 2) {
                float4 pv0 = pr[c4],     xv0 = xv4[c4];
                float4 pv1 = pr[c4 + 1], xv1 = xv4[c4 + 1];
                a0 = fmaf(pv0.x, xv0.x, a0); a0 = fmaf(pv0.y, xv0.y, a0);
                a0 = fmaf(pv0.z, xv0.z, a0); a0 = fmaf(pv0.w, xv0.w, a0);
                a1 = fmaf(pv1.x, xv1.x, a1); a1 = fmaf(pv1.y, xv1.y, a1);
                a1 = fmaf(pv1.z, xv1.z, a1); a1 = fmaf(pv1.w, xv1.w, a1);
            }
            float s = a0 + a1;
            if (s > bv) { bv = s; bi = p; }  // ascending p: first occurrence
        }

        #pragma unroll
        for (int sft = 16; sft >= 1; sft >>= 1) {
            float ov = __shfl_xor_sync(0xffffffffu, bv, sft);
            int   oi = __shfl_xor_sync(0xffffffffu, bi, sft);
            if (ov > bv || (ov == bv && oi < bi)) { bv = ov; bi = oi; }
        }
        if (lane == 0) { rbv[wid] = bv; rbi[wid] = bi; }
        __syncthreads();

        if (tid == 0) {
            float fv = rbv[0]; int fi = rbi[0];
            #pragma unroll
            for (int w = 1; w < 8; ++w)
                if (rbv[w] > fv || (rbv[w] == fv && rbi[w] < fi)) {
                    fv = rbv[w]; fi = rbi[w];
                }
            sfi = fi;
            if (out_size > 16777216LL) out[16777216 + m] = (float)fi;
        }
        __syncthreads();

        // patch recon row for this pixel (c = tid)
        out[(m >> 10) * 262144 + tid * 1024 + (m & 1023)] = proto[(sfi << 8) + tid];
        __syncthreads();
    }
}

// ---------------------------------------------------------------------------
extern "C" void kernel_launch(void* const* d_in, const int* in_sizes, int n_in,
                              void* d_out, int out_size)
{
    const float* x     = (const float*)d_in[0];
    const float* proto = (const float*)d_in[1];
    if (n_in >= 2 && in_sizes[0] == 512 * 256 && in_sizes[1] != 512 * 256) {
        proto = (const float*)d_in[0];
        x     = (const float*)d_in[1];
    }
    float* out = (float*)d_out;

    proto_prep_kernel<<<512, 256>>>(proto);
    xsplit_kernel<<<dim3(4, 32, 64), 256>>>(x);

    cudaFuncSetAttribute(protomatch_mma,
                         cudaFuncAttributeMaxDynamicSharedMemorySize, 181248);
    protomatch_mma<<<256, 512, 181248>>>(proto, out, (long long)out_size);

    fixup_kernel<<<1024, 256>>>(x, proto, out, (long long)out_size);
}

// round 14
// speedup vs baseline: 1.5744x; 1.5744x over previous
#include <cuda_runtime.h>
#include <cuda_fp16.h>
#include <cstdint>
#include <math_constants.h>

// ---------------------------------------------------------------------------
// Device scratch (static: allocation-free)
// ---------------------------------------------------------------------------
__device__ __half g_a [65536 * 256];   // A pixel-major [m][c] = fp16(x)
__device__ __half g_bh[512 * 256];     // normalized proto fp16 [p][c]
__device__ float  g_pnf[512 * 256];    // normalized protos fp32 (for fixup)
__device__ int    g_fixlist[65536];
__device__ int    g_nfix;

__device__ __forceinline__ uint32_t smem_u32(const void* p) {
    uint32_t a;
    asm("{ .reg .u64 t; cvta.to.shared.u64 t, %1; cvt.u32.u64 %0, t; }"
        : "=r"(a) : "l"(p));
    return a;
}
__device__ __forceinline__ void cpa16(uint32_t dst, const void* src) {
    asm volatile("cp.async.cg.shared.global [%0], [%1], 16;"
                 :: "r"(dst), "l"(src));
}
#define LDSM_X4(r0,r1,r2,r3,addr) \
    asm volatile("ldmatrix.sync.aligned.m8n8.x4.shared.b16 {%0,%1,%2,%3}, [%4];" \
        : "=r"(r0),"=r"(r1),"=r"(r2),"=r"(r3) : "r"(addr))
#define MMA16816(d,a,b) \
    asm volatile("mma.sync.aligned.m16n8k16.row.col.f32.f16.f16.f32 " \
        "{%0,%1,%2,%3},{%4,%5,%6,%7},{%8,%9},{%0,%1,%2,%3};" \
        : "+f"(d[0]),"+f"(d[1]),"+f"(d[2]),"+f"(d[3]) \
        : "r"(a[0]),"r"(a[1]),"r"(a[2]),"r"(a[3]),"r"(b[0]),"r"(b[1]))

// fp16-GEMM absolute error std ~3.2e-4; 2.5e-3 threshold = ~8 sigma.
#define FIX_THRESH 2.5e-3f

// ---------------------------------------------------------------------------
// Prep 1: normalize protos -> fp16 + fp32 copies; reset fix counter
// ---------------------------------------------------------------------------
__global__ void proto_prep_kernel(const float* __restrict__ proto) {
    __shared__ float sred[8];
    const int p = blockIdx.x, c = threadIdx.x;
    float v = proto[(p << 8) + c];
    float ss = v * v;
    #pragma unroll
    for (int s = 16; s >= 1; s >>= 1) ss += __shfl_xor_sync(0xffffffffu, ss, s);
    if ((c & 31) == 0) sred[c >> 5] = ss;
    __syncthreads();
    float tot = 0.f;
    #pragma unroll
    for (int w = 0; w < 8; ++w) tot += sred[w];
    const float pn = v / fmaxf(sqrtf(tot), 1e-12f);
    g_pnf[(p << 8) + c] = pn;
    g_bh[(p << 8) + c] = __float2half(pn);
    if (p == 0 && c == 0) g_nfix = 0;
}

// ---------------------------------------------------------------------------
// Prep 2: transpose x [b][c][m] -> A [m][c] fp16, half2 stores.
// grid (4, 32, 64) = (64-ch tiles, 32-m tiles, batch), 256 threads.
// ---------------------------------------------------------------------------
__global__ void xsplit_kernel(const float* __restrict__ x) {
    __shared__ float t[32][66];
    const int b = blockIdx.z, c0 = blockIdx.x << 6, m0 = blockIdx.y << 5;
    const int lane = threadIdx.x & 31, w = threadIdx.x >> 5;
    #pragma unroll
    for (int i = 0; i < 8; ++i) {
        int c = w + (i << 3);
        t[lane][c] = x[b * 262144 + (c0 + c) * 1024 + m0 + lane];
    }
    __syncthreads();
    __half2* ga2 = reinterpret_cast<__half2*>(g_a);
    #pragma unroll
    for (int j = 0; j < 4; ++j) {
        int m = w + (j << 3);
        float2 f = *reinterpret_cast<const float2*>(&t[m][lane << 1]);
        __half2 h = __halves2half2(__float2half(f.x), __float2half(f.y));
        ga2[((size_t)(b * 1024 + m0 + m) << 7) + (c0 >> 1) + lane] = h;
    }
}

// ---------------------------------------------------------------------------
// B slice loader (512 threads): 128 protos x 64 ch fp16 = 16KB into buf (t%3).
// ---------------------------------------------------------------------------
__device__ __forceinline__ void load_bslice(uint32_t Bsm, int t, int tid) {
    const int pc = t >> 2, kb = t & 3;
    const char* src0 = reinterpret_cast<const char*>(g_bh);
    const uint32_t dst = Bsm + (uint32_t)(t % 3) * 16384u;
    #pragma unroll
    for (int i = 0; i < 2; ++i) {
        int u = tid + (i << 9);          // 0..1023 16B units
        int r = u >> 3, c = u & 7;
        uint32_t o = (uint32_t)(r << 7) + (uint32_t)(c << 4);
        const char* src = src0 + (size_t)(pc * 128 + r) * 512 + kb * 128 + (c << 4);
        cpa16(dst + (o ^ ((o >> 3) & 0x70)), src);
    }
}

// ---------------------------------------------------------------------------
// Main: 256 blocks x 256 pixels, 512 threads (16 warps, 4m x 4n warp grid,
// 64x32 tile/warp). A (256x256 fp16, 128KB) staged once; 16 B slices (16KB)
// 3-stage pipelined. fp16 GEMM, fp32 acc, top-2 + fused gather epilogue.
// ---------------------------------------------------------------------------
__global__ __launch_bounds__(512, 1)
void protomatch_mma(const float* __restrict__ proto,
                    float* __restrict__ out, long long out_size)
{
    extern __shared__ char dsm[];
    const uint32_t dynb = smem_u32(dsm);
    const uint32_t base = (dynb + 1023u) & ~1023u;
    char* base_g = dsm + (base - dynb);
    const uint32_t Asm = base;            // 131072 bytes (4 chunks x 32KB)
    const uint32_t Bsm = base + 131072u;  // 49152 bytes (3 bufs x 16KB)

    const int tid = threadIdx.x, lane = tid & 31, wid = tid >> 5;
    const int warp_m = wid & 3, warp_n = wid >> 2;   // 4 x 4
    const int m0 = blockIdx.x << 8;      // 256 pixels per block
    const int b = m0 >> 10, n0 = m0 & 1023;

    // ---- stage A (256 rows x 256 fp16 = 128KB) + first two B slices ----
    const char* Ag = reinterpret_cast<const char*>(g_a);
    #pragma unroll
    for (int i = 0; i < 16; ++i) {
        int u = tid + (i << 9);          // 0..8191 16B units
        int s = u >> 11;                 // chunk 0..3 (2048 units each)
        int r = (u >> 3) & 255;          // row 0..255
        int c = u & 7;                   // 16B col 0..7
        uint32_t o = (uint32_t)(r << 7) + (uint32_t)(c << 4);
        cpa16(Asm + (s << 15) + (o ^ ((o >> 3) & 0x70)),
              Ag + (size_t)(m0 + r) * 512 + (s << 7) + (c << 4));
    }
    load_bslice(Bsm, 0, tid);
    asm volatile("cp.async.commit_group;");
    load_bslice(Bsm, 1, tid);
    asm volatile("cp.async.commit_group;");

    // per-lane ldmatrix address components: 4 m-tiles of 16 rows per warp
    uint32_t aoff[4], aswz[4];
    #pragma unroll
    for (int mt = 0; mt < 4; ++mt) {
        int rowA = warp_m * 64 + mt * 16 + (lane & 15);
        aoff[mt] = (uint32_t)rowA << 7;
        aswz[mt] = (uint32_t)(rowA & 7);
    }
    const uint32_t alc = (uint32_t)(lane >> 4);        // k-half select for A

    uint32_t boff[2], bswz[2];
    #pragma unroll
    for (int nt2 = 0; nt2 < 2; ++nt2) {
        int rowB = warp_n * 32 + nt2 * 16 + ((lane >> 4) << 3) + (lane & 7);
        boff[nt2] = (uint32_t)rowB << 7;
        bswz[nt2] = (uint32_t)(rowB & 7);
    }
    const uint32_t blc = (uint32_t)((lane >> 3) & 1);  // k-half select for B

    float acc[4][4][4];
    float t1v[8], t2v[8];
    int   t1i[8];
    #pragma unroll
    for (int s = 0; s < 8; ++s) { t1v[s] = -CUDART_INF_F; t2v[s] = -CUDART_INF_F; t1i[s] = 0; }

    for (int t = 0; t < 16; ++t) {
        const int pc = t >> 2, kb = t & 3;
        if (kb == 0) {
            #pragma unroll
            for (int i = 0; i < 4; ++i)
                #pragma unroll
                for (int j = 0; j < 4; ++j)
                    #pragma unroll
                    for (int q = 0; q < 4; ++q) acc[i][j][q] = 0.f;
        }
        // pipeline: wait(tile t ready) -> sync -> issue copy t+2 -> compute
        if (t < 15) asm volatile("cp.async.wait_group 1;");
        else        asm volatile("cp.async.wait_group 0;");
        __syncthreads();
        if (t + 2 < 16) {
            load_bslice(Bsm, t + 2, tid);
            asm volatile("cp.async.commit_group;");
        }

        const uint32_t Ab = Asm + ((uint32_t)kb << 15);
        const uint32_t Bb = Bsm + (uint32_t)(t % 3) * 16384u;

        #pragma unroll
        for (int k16 = 0; k16 < 4; ++k16) {
            uint32_t ra[4][4];
            #pragma unroll
            for (int mt = 0; mt < 4; ++mt) {
                uint32_t c16 = (uint32_t)(k16 << 1) + alc;
                LDSM_X4(ra[mt][0], ra[mt][1], ra[mt][2], ra[mt][3],
                        Ab + aoff[mt] + ((c16 ^ aswz[mt]) << 4));
            }
            #pragma unroll
            for (int nt2 = 0; nt2 < 2; ++nt2) {
                uint32_t c16 = (uint32_t)(k16 << 1) + blc;
                uint32_t rb[4];
                LDSM_X4(rb[0], rb[1], rb[2], rb[3],
                        Bb + boff[nt2] + ((c16 ^ bswz[nt2]) << 4));
                #pragma unroll
                for (int mt = 0; mt < 4; ++mt) {
                    MMA16816(acc[mt][2*nt2+0], ra[mt], (rb + 0));
                    MMA16816(acc[mt][2*nt2+1], ra[mt], (rb + 2));
                }
            }
        }

        if (kb == 3) {     // fold chunk pc into running top-2
            #pragma unroll
            for (int mt = 0; mt < 4; ++mt)
                #pragma unroll
                for (int rh = 0; rh < 2; ++rh) {
                    int sl = mt * 2 + rh;
                    #pragma unroll
                    for (int nt = 0; nt < 4; ++nt)
                        #pragma unroll
                        for (int e = 0; e < 2; ++e) {
                            float v = acc[mt][nt][rh * 2 + e];
                            int col = (pc << 7) + (warp_n << 5) + (nt << 3)
                                    + ((lane & 3) << 1) + e;
                            if (v > t1v[sl]) { t2v[sl] = t1v[sl]; t1v[sl] = v; t1i[sl] = col; }
                            else if (v > t2v[sl]) t2v[sl] = v;
                        }
                }
        }
    }
    __syncthreads();

    // ---- cross-lane/warp reduction via smem (reuse A region) ----
    float* sv1 = reinterpret_cast<float*>(base_g);            // [256][16]
    int*   si1 = reinterpret_cast<int*>(base_g + 16384);
    float* sv2 = reinterpret_cast<float*>(base_g + 32768);
    int*   sIdx = reinterpret_cast<int*>(base_g + 49152);     // [256]
    #pragma unroll
    for (int mt = 0; mt < 4; ++mt)
        #pragma unroll
        for (int rh = 0; rh < 2; ++rh) {
            int sl = mt * 2 + rh;
            int row = warp_m * 64 + mt * 16 + rh * 8 + (lane >> 2);
            int cand = (warp_n << 2) + (lane & 3);
            sv1[row * 16 + cand] = t1v[sl];
            si1[row * 16 + cand] = t1i[sl];
            sv2[row * 16 + cand] = t2v[sl];
        }
    __syncthreads();

    if (tid < 256) {
        float v1 = -CUDART_INF_F, v2 = -CUDART_INF_F;
        int i1 = 0x7fffffff;
        #pragma unroll
        for (int c = 0; c < 16; ++c) {
            float cv1 = sv1[tid * 16 + c], cv2 = sv2[tid * 16 + c];
            int   ci1 = si1[tid * 16 + c];
            if (cv1 > v1 || (cv1 == v1 && ci1 < i1)) {
                v2 = fmaxf(v1, cv2); v1 = cv1; i1 = ci1;
            } else {
                v2 = fmaxf(v2, cv1);
            }
        }
        const int m = m0 + tid;
        sIdx[tid] = i1;
        if (out_size > 16777216LL) out[16777216 + m] = (float)i1;
        if (v1 - v2 < FIX_THRESH) {
            int pos = atomicAdd(&g_nfix, 1);
            g_fixlist[pos] = m;
        }
    }
    __syncthreads();

    // ---- fused gather: recon[b,c,h,w] = proto[idx][c], coalesced ----
    const int n4 = tid & 63;   // float4 col within 256-pixel tile
    const int ph = tid >> 6;   // channel phase 0..7
    const float* r0 = proto + (sIdx[(n4 << 2) + 0] << 8);
    const float* r1 = proto + (sIdx[(n4 << 2) + 1] << 8);
    const float* r2 = proto + (sIdx[(n4 << 2) + 2] << 8);
    const float* r3 = proto + (sIdx[(n4 << 2) + 3] << 8);
    float4* Og = reinterpret_cast<float4*>(out) + (b * 65536 + (n0 >> 2) + n4);
    #pragma unroll 4
    for (int c = ph; c < 256; c += 8)
        Og[c * 256] = make_float4(r0[c], r1[c], r2[c], r3[c]);
}

// ---------------------------------------------------------------------------
// Fixup: exact fp32 argmax for flagged pixels, 8 entries/block (measured-best
// amortization of the 512KB proto-bank stream), grid 256; patches recon rows.
// ---------------------------------------------------------------------------
__global__ __launch_bounds__(256)
void fixup_kernel(const float* __restrict__ x, const float* __restrict__ proto,
                  float* __restrict__ out, long long out_size)
{
    __shared__ __align__(16) float xs[8][260];
    __shared__ float rbv[8][8];
    __shared__ int   rbi[8][8];
    __shared__ int   sfi[8];
    const int tid = threadIdx.x, lane = tid & 31, wid = tid >> 5;
    const int nfix = g_nfix;

    for (int g0 = blockIdx.x * 8; g0 < nfix; g0 += gridDim.x * 8) {
        const int ne = min(8, nfix - g0);
        for (int i = tid; i < (ne << 8); i += 256) {
            int e = i >> 8, c = i & 255;
            int m = g_fixlist[g0 + e];
            xs[e][c] = x[(m >> 10) * 262144 + c * 1024 + (m & 1023)];
        }
        __syncthreads();

        float bv[8]; int bi[8];
        #pragma unroll
        for (int e = 0; e < 8; ++e) { bv[e] = -CUDART_INF_F; bi[e] = 0; }

        #pragma unroll
        for (int h = 0; h < 2; ++h) {
            const int p = tid + (h << 8);
            const float4* pr = reinterpret_cast<const float4*>(g_pnf + (p << 8));
            float acc[8];
            #pragma unroll
            for (int e = 0; e < 8; ++e) acc[e] = 0.f;
            #pragma unroll 4
            for (int c4 = 0; c4 < 64; ++c4) {
                float4 pv = pr[c4];
                #pragma unroll
                for (int e = 0; e < 8; ++e) {
                    float4 xv = reinterpret_cast<const float4*>(xs[e])[c4];
                    acc[e] = fmaf(pv.x, xv.x, acc[e]);
                    acc[e] = fmaf(pv.y, xv.y, acc[e]);
                    acc[e] = fmaf(pv.z, xv.z, acc[e]);
                    acc[e] = fmaf(pv.w, xv.w, acc[e]);
                }
            }
            #pragma unroll
            for (int e = 0; e < 8; ++e)
                if (acc[e] > bv[e]) { bv[e] = acc[e]; bi[e] = p; }  // ascending p
        }

        #pragma unroll
        for (int e = 0; e < 8; ++e) {
            float v = bv[e]; int ix = bi[e];
            #pragma unroll
            for (int s = 16; s >= 1; s >>= 1) {
                float ov = __shfl_xor_sync(0xffffffffu, v, s);
                int   oi = __shfl_xor_sync(0xffffffffu, ix, s);
                if (ov > v || (ov == v && oi < ix)) { v = ov; ix = oi; }
            }
            if (lane == 0) { rbv[e][wid] = v; rbi[e][wid] = ix; }
        }
        __syncthreads();

        if (tid < ne) {
            float fv = rbv[tid][0]; int fi = rbi[tid][0];
            #pragma unroll
            for (int w = 1; w < 8; ++w)
                if (rbv[tid][w] > fv || (rbv[tid][w] == fv && rbi[tid][w] < fi)) {
                    fv = rbv[tid][w]; fi = rbi[tid][w];
                }
            sfi[tid] = fi;
            const int m = g_fixlist[g0 + tid];
            if (out_size > 16777216LL) out[16777216 + m] = (float)fi;
        }
        __syncthreads();

        // patch recon rows for corrected pixels (c = tid)
        for (int e = 0; e < ne; ++e) {
            const int m = g_fixlist[g0 + e];
            out[(m >> 10) * 262144 + tid * 1024 + (m & 1023)] = proto[(sfi[e] << 8) + tid];
        }
        __syncthreads();
    }
}

// ---------------------------------------------------------------------------
extern "C" void kernel_launch(void* const* d_in, const int* in_sizes, int n_in,
                              void* d_out, int out_size)
{
    const float* x     = (const float*)d_in[0];
    const float* proto = (const float*)d_in[1];
    if (n_in >= 2 && in_sizes[0] == 512 * 256 && in_sizes[1] != 512 * 256) {
        proto = (const float*)d_in[0];
        x     = (const float*)d_in[1];
    }
    float* out = (float*)d_out;

    proto_prep_kernel<<<512, 256>>>(proto);
    xsplit_kernel<<<dim3(4, 32, 64), 256>>>(x);

    cudaFuncSetAttribute(protomatch_mma,
                         cudaFuncAttributeMaxDynamicSharedMemorySize, 181248);
    protomatch_mma<<<256, 512, 181248>>>(proto, out, (long long)out_size);

    fixup_kernel<<<256, 256>>>(x, proto, out, (long long)out_size);
}

// round 15
// speedup vs baseline: 1.5895x; 1.0096x over previous
#include <cuda_runtime.h>
#include <cuda_fp16.h>
#include <cstdint>
#include <math_constants.h>

// ---------------------------------------------------------------------------
// Device scratch (static: allocation-free)
// ---------------------------------------------------------------------------
__device__ __half g_a [65536 * 256];   // A pixel-major [m][c] = fp16(x)
__device__ __half g_bh[512 * 256];     // normalized proto fp16 [p][c]
__device__ float  g_pnf[512 * 256];    // normalized protos fp32 (for fixup)
__device__ int    g_fixlist[65536];
__device__ int    g_nfix;

__device__ __forceinline__ uint32_t smem_u32(const void* p) {
    uint32_t a;
    asm("{ .reg .u64 t; cvta.to.shared.u64 t, %1; cvt.u32.u64 %0, t; }"
        : "=r"(a) : "l"(p));
    return a;
}
__device__ __forceinline__ void cpa16(uint32_t dst, const void* src) {
    asm volatile("cp.async.cg.shared.global [%0], [%1], 16;"
                 :: "r"(dst), "l"(src));
}
#define LDSM_X4(r0,r1,r2,r3,addr) \
    asm volatile("ldmatrix.sync.aligned.m8n8.x4.shared.b16 {%0,%1,%2,%3}, [%4];" \
        : "=r"(r0),"=r"(r1),"=r"(r2),"=r"(r3) : "r"(addr))
#define MMA16816(d,a,b) \
    asm volatile("mma.sync.aligned.m16n8k16.row.col.f32.f16.f16.f32 " \
        "{%0,%1,%2,%3},{%4,%5,%6,%7},{%8,%9},{%0,%1,%2,%3};" \
        : "+f"(d[0]),"+f"(d[1]),"+f"(d[2]),"+f"(d[3]) \
        : "r"(a[0]),"r"(a[1]),"r"(a[2]),"r"(a[3]),"r"(b[0]),"r"(b[1]))

// fp16-GEMM absolute error std ~3.2e-4; 2.5e-3 threshold = ~8 sigma.
#define FIX_THRESH 2.5e-3f

// ---------------------------------------------------------------------------
// Prep 1: normalize protos -> fp16 + fp32 copies; reset fix counter
// ---------------------------------------------------------------------------
__global__ void proto_prep_kernel(const float* __restrict__ proto) {
    __shared__ float sred[8];
    const int p = blockIdx.x, c = threadIdx.x;
    float v = proto[(p << 8) + c];
    float ss = v * v;
    #pragma unroll
    for (int s = 16; s >= 1; s >>= 1) ss += __shfl_xor_sync(0xffffffffu, ss, s);
    if ((c & 31) == 0) sred[c >> 5] = ss;
    __syncthreads();
    float tot = 0.f;
    #pragma unroll
    for (int w = 0; w < 8; ++w) tot += sred[w];
    const float pn = v / fmaxf(sqrtf(tot), 1e-12f);
    g_pnf[(p << 8) + c] = pn;
    g_bh[(p << 8) + c] = __float2half(pn);
    if (p == 0 && c == 0) g_nfix = 0;
}

// ---------------------------------------------------------------------------
// Prep 2: transpose x [b][c][m] -> A [m][c] fp16, half2 stores.
// grid (4, 32, 64) = (64-ch tiles, 32-m tiles, batch), 256 threads.
// ---------------------------------------------------------------------------
__global__ void xsplit_kernel(const float* __restrict__ x) {
    __shared__ float t[32][66];
    const int b = blockIdx.z, c0 = blockIdx.x << 6, m0 = blockIdx.y << 5;
    const int lane = threadIdx.x & 31, w = threadIdx.x >> 5;
    #pragma unroll
    for (int i = 0; i < 8; ++i) {
        int c = w + (i << 3);
        t[lane][c] = x[b * 262144 + (c0 + c) * 1024 + m0 + lane];
    }
    __syncthreads();
    __half2* ga2 = reinterpret_cast<__half2*>(g_a);
    #pragma unroll
    for (int j = 0; j < 4; ++j) {
        int m = w + (j << 3);
        float2 f = *reinterpret_cast<const float2*>(&t[m][lane << 1]);
        __half2 h = __halves2half2(__float2half(f.x), __float2half(f.y));
        ga2[((size_t)(b * 1024 + m0 + m) << 7) + (c0 >> 1) + lane] = h;
    }
}

// ---------------------------------------------------------------------------
// B slice loader (512 threads): 128 protos x 64 ch fp16 = 16KB into buf (t%3).
// ---------------------------------------------------------------------------
__device__ __forceinline__ void load_bslice(uint32_t Bsm, int t, int tid) {
    const int pc = t >> 2, kb = t & 3;
    const char* src0 = reinterpret_cast<const char*>(g_bh);
    const uint32_t dst = Bsm + (uint32_t)(t % 3) * 16384u;
    #pragma unroll
    for (int i = 0; i < 2; ++i) {
        int u = tid + (i << 9);          // 0..1023 16B units
        int r = u >> 3, c = u & 7;
        uint32_t o = (uint32_t)(r << 7) + (uint32_t)(c << 4);
        const char* src = src0 + (size_t)(pc * 128 + r) * 512 + kb * 128 + (c << 4);
        cpa16(dst + (o ^ ((o >> 3) & 0x70)), src);
    }
}

// ---------------------------------------------------------------------------
// Main: 256 blocks x 256 pixels, 512 threads (16 warps, 4m x 4n warp grid,
// 64x32 tile/warp). A (256x256 fp16, 128KB) staged once; 16 B slices (16KB)
// 3-stage pipelined. fp16 GEMM, fp32 acc, top-2 + fused gather epilogue.
// ---------------------------------------------------------------------------
__global__ __launch_bounds__(512, 1)
void protomatch_mma(const float* __restrict__ proto,
                    float* __restrict__ out, long long out_size)
{
    extern __shared__ char dsm[];
    const uint32_t dynb = smem_u32(dsm);
    const uint32_t base = (dynb + 1023u) & ~1023u;
    char* base_g = dsm + (base - dynb);
    const uint32_t Asm = base;            // 131072 bytes (4 chunks x 32KB)
    const uint32_t Bsm = base + 131072u;  // 49152 bytes (3 bufs x 16KB)

    const int tid = threadIdx.x, lane = tid & 31, wid = tid >> 5;
    const int warp_m = wid & 3, warp_n = wid >> 2;   // 4 x 4
    const int m0 = blockIdx.x << 8;      // 256 pixels per block
    const int b = m0 >> 10, n0 = m0 & 1023;

    // ---- stage A (256 rows x 256 fp16 = 128KB) + first two B slices ----
    const char* Ag = reinterpret_cast<const char*>(g_a);
    #pragma unroll
    for (int i = 0; i < 16; ++i) {
        int u = tid + (i << 9);          // 0..8191 16B units
        int s = u >> 11;                 // chunk 0..3 (2048 units each)
        int r = (u >> 3) & 255;          // row 0..255
        int c = u & 7;                   // 16B col 0..7
        uint32_t o = (uint32_t)(r << 7) + (uint32_t)(c << 4);
        cpa16(Asm + (s << 15) + (o ^ ((o >> 3) & 0x70)),
              Ag + (size_t)(m0 + r) * 512 + (s << 7) + (c << 4));
    }
    load_bslice(Bsm, 0, tid);
    asm volatile("cp.async.commit_group;");
    load_bslice(Bsm, 1, tid);
    asm volatile("cp.async.commit_group;");

    // per-lane ldmatrix address components: 4 m-tiles of 16 rows per warp
    uint32_t aoff[4], aswz[4];
    #pragma unroll
    for (int mt = 0; mt < 4; ++mt) {
        int rowA = warp_m * 64 + mt * 16 + (lane & 15);
        aoff[mt] = (uint32_t)rowA << 7;
        aswz[mt] = (uint32_t)(rowA & 7);
    }
    const uint32_t alc = (uint32_t)(lane >> 4);        // k-half select for A

    uint32_t boff[2], bswz[2];
    #pragma unroll
    for (int nt2 = 0; nt2 < 2; ++nt2) {
        int rowB = warp_n * 32 + nt2 * 16 + ((lane >> 4) << 3) + (lane & 7);
        boff[nt2] = (uint32_t)rowB << 7;
        bswz[nt2] = (uint32_t)(rowB & 7);
    }
    const uint32_t blc = (uint32_t)((lane >> 3) & 1);  // k-half select for B

    float acc[4][4][4];
    float t1v[8], t2v[8];
    int   t1i[8];
    #pragma unroll
    for (int s = 0; s < 8; ++s) { t1v[s] = -CUDART_INF_F; t2v[s] = -CUDART_INF_F; t1i[s] = 0; }

    for (int t = 0; t < 16; ++t) {
        const int pc = t >> 2, kb = t & 3;
        if (kb == 0) {
            #pragma unroll
            for (int i = 0; i < 4; ++i)
                #pragma unroll
                for (int j = 0; j < 4; ++j)
                    #pragma unroll
                    for (int q = 0; q < 4; ++q) acc[i][j][q] = 0.f;
        }
        // pipeline: wait(tile t ready) -> sync -> issue copy t+2 -> compute
        if (t < 15) asm volatile("cp.async.wait_group 1;");
        else        asm volatile("cp.async.wait_group 0;");
        __syncthreads();
        if (t + 2 < 16) {
            load_bslice(Bsm, t + 2, tid);
            asm volatile("cp.async.commit_group;");
        }

        const uint32_t Ab = Asm + ((uint32_t)kb << 15);
        const uint32_t Bb = Bsm + (uint32_t)(t % 3) * 16384u;

        #pragma unroll
        for (int k16 = 0; k16 < 4; ++k16) {
            uint32_t ra[4][4];
            #pragma unroll
            for (int mt = 0; mt < 4; ++mt) {
                uint32_t c16 = (uint32_t)(k16 << 1) + alc;
                LDSM_X4(ra[mt][0], ra[mt][1], ra[mt][2], ra[mt][3],
                        Ab + aoff[mt] + ((c16 ^ aswz[mt]) << 4));
            }
            #pragma unroll
            for (int nt2 = 0; nt2 < 2; ++nt2) {
                uint32_t c16 = (uint32_t)(k16 << 1) + blc;
                uint32_t rb[4];
                LDSM_X4(rb[0], rb[1], rb[2], rb[3],
                        Bb + boff[nt2] + ((c16 ^ bswz[nt2]) << 4));
                #pragma unroll
                for (int mt = 0; mt < 4; ++mt) {
                    MMA16816(acc[mt][2*nt2+0], ra[mt], (rb + 0));
                    MMA16816(acc[mt][2*nt2+1], ra[mt], (rb + 2));
                }
            }
        }

        if (kb == 3) {     // fold chunk pc into running top-2
            #pragma unroll
            for (int mt = 0; mt < 4; ++mt)
                #pragma unroll
                for (int rh = 0; rh < 2; ++rh) {
                    int sl = mt * 2 + rh;
                    #pragma unroll
                    for (int nt = 0; nt < 4; ++nt)
                        #pragma unroll
                        for (int e = 0; e < 2; ++e) {
                            float v = acc[mt][nt][rh * 2 + e];
                            int col = (pc << 7) + (warp_n << 5) + (nt << 3)
                                    + ((lane & 3) << 1) + e;
                            if (v > t1v[sl]) { t2v[sl] = t1v[sl]; t1v[sl] = v; t1i[sl] = col; }
                            else if (v > t2v[sl]) t2v[sl] = v;
                        }
                }
        }
    }
    __syncthreads();

    // ---- cross-lane/warp reduction via smem (reuse A region) ----
    float* sv1 = reinterpret_cast<float*>(base_g);            // [256][16]
    int*   si1 = reinterpret_cast<int*>(base_g + 16384);
    float* sv2 = reinterpret_cast<float*>(base_g + 32768);
    int*   sIdx = reinterpret_cast<int*>(base_g + 49152);     // [256]
    #pragma unroll
    for (int mt = 0; mt < 4; ++mt)
        #pragma unroll
        for (int rh = 0; rh < 2; ++rh) {
            int sl = mt * 2 + rh;
            int row = warp_m * 64 + mt * 16 + rh * 8 + (lane >> 2);
            int cand = (warp_n << 2) + (lane & 3);
            sv1[row * 16 + cand] = t1v[sl];
            si1[row * 16 + cand] = t1i[sl];
            sv2[row * 16 + cand] = t2v[sl];
        }
    __syncthreads();

    if (tid < 256) {
        float v1 = -CUDART_INF_F, v2 = -CUDART_INF_F;
        int i1 = 0x7fffffff;
        #pragma unroll
        for (int c = 0; c < 16; ++c) {
            float cv1 = sv1[tid * 16 + c], cv2 = sv2[tid * 16 + c];
            int   ci1 = si1[tid * 16 + c];
            if (cv1 > v1 || (cv1 == v1 && ci1 < i1)) {
                v2 = fmaxf(v1, cv2); v1 = cv1; i1 = ci1;
            } else {
                v2 = fmaxf(v2, cv1);
            }
        }
        const int m = m0 + tid;
        sIdx[tid] = i1;
        if (out_size > 16777216LL) out[16777216 + m] = (float)i1;
        if (v1 - v2 < FIX_THRESH) {
            int pos = atomicAdd(&g_nfix, 1);
            g_fixlist[pos] = m;
        }
    }
    __syncthreads();

    // ---- fused gather: recon[b,c,h,w] = proto[idx][c], coalesced ----
    const int n4 = tid & 63;   // float4 col within 256-pixel tile
    const int ph = tid >> 6;   // channel phase 0..7
    const float* r0 = proto + (sIdx[(n4 << 2) + 0] << 8);
    const float* r1 = proto + (sIdx[(n4 << 2) + 1] << 8);
    const float* r2 = proto + (sIdx[(n4 << 2) + 2] << 8);
    const float* r3 = proto + (sIdx[(n4 << 2) + 3] << 8);
    float4* Og = reinterpret_cast<float4*>(out) + (b * 65536 + (n0 >> 2) + n4);
    #pragma unroll 4
    for (int c = ph; c < 256; c += 8)
        Og[c * 256] = make_float4(r0[c], r1[c], r2[c], r3[c]);
}

// ---------------------------------------------------------------------------
// Fixup: exact fp32 argmax for flagged pixels, 8 entries/block, 512 threads:
// each thread owns exactly ONE proto (halved sequential depth vs 256-thread
// version). Patches recon rows of corrected pixels.
// ---------------------------------------------------------------------------
__global__ __launch_bounds__(512)
void fixup_kernel(const float* __restrict__ x, const float* __restrict__ proto,
                  float* __restrict__ out, long long out_size)
{
    __shared__ __align__(16) float xs[8][260];
    __shared__ float rbv[8][16];
    __shared__ int   rbi[8][16];
    __shared__ int   sfi[8];
    const int tid = threadIdx.x, lane = tid & 31, wid = tid >> 5;  // 16 warps
    const int nfix = g_nfix;

    for (int g0 = blockIdx.x * 8; g0 < nfix; g0 += gridDim.x * 8) {
        const int ne = min(8, nfix - g0);
        for (int i = tid; i < (ne << 8); i += 512) {
            int e = i >> 8, c = i & 255;
            int m = g_fixlist[g0 + e];
            xs[e][c] = x[(m >> 10) * 262144 + c * 1024 + (m & 1023)];
        }
        __syncthreads();

        // one proto per thread: p = tid (0..511)
        const float4* pr = reinterpret_cast<const float4*>(g_pnf + (tid << 8));
        float acc[8];
        #pragma unroll
        for (int e = 0; e < 8; ++e) acc[e] = 0.f;
        #pragma unroll 4
        for (int c4 = 0; c4 < 64; ++c4) {
            float4 pv = pr[c4];
            #pragma unroll
            for (int e = 0; e < 8; ++e) {
                float4 xv = reinterpret_cast<const float4*>(xs[e])[c4];
                acc[e] = fmaf(pv.x, xv.x, acc[e]);
                acc[e] = fmaf(pv.y, xv.y, acc[e]);
                acc[e] = fmaf(pv.z, xv.z, acc[e]);
                acc[e] = fmaf(pv.w, xv.w, acc[e]);
            }
        }

        // warp-reduce each entry (proto ids ascending with lane; ties -> lower)
        #pragma unroll
        for (int e = 0; e < 8; ++e) {
            float v = acc[e]; int ix = tid;
            #pragma unroll
            for (int s = 16; s >= 1; s >>= 1) {
                float ov = __shfl_xor_sync(0xffffffffu, v, s);
                int   oi = __shfl_xor_sync(0xffffffffu, ix, s);
                if (ov > v || (ov == v && oi < ix)) { v = ov; ix = oi; }
            }
            if (lane == 0) { rbv[e][wid] = v; rbi[e][wid] = ix; }
        }
        __syncthreads();

        if (tid < ne) {
            float fv = rbv[tid][0]; int fi = rbi[tid][0];
            #pragma unroll
            for (int w = 1; w < 16; ++w)
                if (rbv[tid][w] > fv || (rbv[tid][w] == fv && rbi[tid][w] < fi)) {
                    fv = rbv[tid][w]; fi = rbi[tid][w];
                }
            sfi[tid] = fi;
            const int m = g_fixlist[g0 + tid];
            if (out_size > 16777216LL) out[16777216 + m] = (float)fi;
        }
        __syncthreads();

        // patch recon rows: channel c = tid&255; thread-half covers entries
        // eh, eh+2, eh+4, eh+6
        const int c  = tid & 255;
        const int eh = tid >> 8;
        for (int e = eh; e < ne; e += 2) {
            const int m = g_fixlist[g0 + e];
            out[(m >> 10) * 262144 + c * 1024 + (m & 1023)] = proto[(sfi[e] << 8) + c];
        }
        __syncthreads();
    }
}

// ---------------------------------------------------------------------------
extern "C" void kernel_launch(void* const* d_in, const int* in_sizes, int n_in,
                              void* d_out, int out_size)
{
    const float* x     = (const float*)d_in[0];
    const float* proto = (const float*)d_in[1];
    if (n_in >= 2 && in_sizes[0] == 512 * 256 && in_sizes[1] != 512 * 256) {
        proto = (const float*)d_in[0];
        x     = (const float*)d_in[1];
    }
    float* out = (float*)d_out;

    proto_prep_kernel<<<512, 256>>>(proto);
    xsplit_kernel<<<dim3(4, 32, 64), 256>>>(x);

    cudaFuncSetAttribute(protomatch_mma,
                         cudaFuncAttributeMaxDynamicSharedMemorySize, 181248);
    protomatch_mma<<<256, 512, 181248>>>(proto, out, (long long)out_size);

    fixup_kernel<<<256, 512>>>(x, proto, out, (long long)out_size);
}

// round 16
// speedup vs baseline: 1.6029x; 1.0084x over previous
#include <cuda_runtime.h>
#include <cuda_fp16.h>
#include <cstdint>
#include <math_constants.h>

// ---------------------------------------------------------------------------
// Device scratch (static: allocation-free)
// ---------------------------------------------------------------------------
__device__ __half g_a [65536 * 256];   // A pixel-major [m][c] = fp16(x)
__device__ __half g_bh[512 * 256];     // normalized proto fp16 [p][c]
__device__ float  g_pnf[512 * 256];    // normalized protos fp32 (for fixup)
__device__ int    g_fixlist[65536];
__device__ int    g_nfix;

__device__ __forceinline__ uint32_t smem_u32(const void* p) {
    uint32_t a;
    asm("{ .reg .u64 t; cvta.to.shared.u64 t, %1; cvt.u32.u64 %0, t; }"
        : "=r"(a) : "l"(p));
    return a;
}
__device__ __forceinline__ void cpa16(uint32_t dst, const void* src) {
    asm volatile("cp.async.cg.shared.global [%0], [%1], 16;"
                 :: "r"(dst), "l"(src));
}
#define LDSM_X4(r0,r1,r2,r3,addr) \
    asm volatile("ldmatrix.sync.aligned.m8n8.x4.shared.b16 {%0,%1,%2,%3}, [%4];" \
        : "=r"(r0),"=r"(r1),"=r"(r2),"=r"(r3) : "r"(addr))
#define MMA16816(d,a,b) \
    asm volatile("mma.sync.aligned.m16n8k16.row.col.f32.f16.f16.f32 " \
        "{%0,%1,%2,%3},{%4,%5,%6,%7},{%8,%9},{%0,%1,%2,%3};" \
        : "+f"(d[0]),"+f"(d[1]),"+f"(d[2]),"+f"(d[3]) \
        : "r"(a[0]),"r"(a[1]),"r"(a[2]),"r"(a[3]),"r"(b[0]),"r"(b[1]))

// fp16-GEMM absolute error std ~3.2e-4; 2.5e-3 threshold = ~8 sigma.
#define FIX_THRESH 2.5e-3f

// ---------------------------------------------------------------------------
// Prep 1: normalize protos -> fp16 + fp32 copies; reset fix counter
// ---------------------------------------------------------------------------
__global__ void proto_prep_kernel(const float* __restrict__ proto) {
    __shared__ float sred[8];
    const int p = blockIdx.x, c = threadIdx.x;
    float v = proto[(p << 8) + c];
    float ss = v * v;
    #pragma unroll
    for (int s = 16; s >= 1; s >>= 1) ss += __shfl_xor_sync(0xffffffffu, ss, s);
    if ((c & 31) == 0) sred[c >> 5] = ss;
    __syncthreads();
    float tot = 0.f;
    #pragma unroll
    for (int w = 0; w < 8; ++w) tot += sred[w];
    const float pn = v / fmaxf(sqrtf(tot), 1e-12f);
    g_pnf[(p << 8) + c] = pn;
    g_bh[(p << 8) + c] = __float2half(pn);
    if (p == 0 && c == 0) g_nfix = 0;
}

// ---------------------------------------------------------------------------
// Prep 2: transpose x [b][c][m] -> A [m][c] fp16, half2 stores.
// ---------------------------------------------------------------------------
__global__ void xsplit_kernel(const float* __restrict__ x) {
    __shared__ float t[32][66];
    const int b = blockIdx.z, c0 = blockIdx.x << 6, m0 = blockIdx.y << 5;
    const int lane = threadIdx.x & 31, w = threadIdx.x >> 5;
    #pragma unroll
    for (int i = 0; i < 8; ++i) {
        int c = w + (i << 3);
        t[lane][c] = x[b * 262144 + (c0 + c) * 1024 + m0 + lane];
    }
    __syncthreads();
    __half2* ga2 = reinterpret_cast<__half2*>(g_a);
    #pragma unroll
    for (int j = 0; j < 4; ++j) {
        int m = w + (j << 3);
        float2 f = *reinterpret_cast<const float2*>(&t[m][lane << 1]);
        __half2 h = __halves2half2(__float2half(f.x), __float2half(f.y));
        ga2[((size_t)(b * 1024 + m0 + m) << 7) + (c0 >> 1) + lane] = h;
    }
}

// ---------------------------------------------------------------------------
// B slice loader (256 threads): 128 protos x 64 ch fp16 = 16KB into buf (t%3).
// ---------------------------------------------------------------------------
__device__ __forceinline__ void load_bslice(uint32_t Bsm, int t, int tid) {
    const int pc = t >> 2, kb = t & 3;
    const char* src0 = reinterpret_cast<const char*>(g_bh);
    const uint32_t dst = Bsm + (uint32_t)(t % 3) * 16384u;
    #pragma unroll
    for (int i = 0; i < 4; ++i) {
        int u = tid + (i << 8);          // 0..1023 16B units
        int r = u >> 3, c = u & 7;
        uint32_t o = (uint32_t)(r << 7) + (uint32_t)(c << 4);
        const char* src = src0 + (size_t)(pc * 128 + r) * 512 + kb * 128 + (c << 4);
        cpa16(dst + (o ^ ((o >> 3) & 0x70)), src);
    }
}

// ---------------------------------------------------------------------------
// Main: 512 blocks x 128 pixels, 256 threads (8 warps, 4m x 2n grid,
// 32x64 tile/warp), smem 113KB -> TWO CTAs per SM (barrier bubbles of one
// CTA hidden by the other). A (128x256 fp16, 64KB) staged once; 16 B slices
// 3-stage pipelined. fp16 GEMM, fp32 acc, top-2 + fused gather epilogue.
// ---------------------------------------------------------------------------
__global__ __launch_bounds__(256, 2)
void protomatch_mma(const float* __restrict__ proto,
                    float* __restrict__ out, long long out_size)
{
    extern __shared__ char dsm[];
    const uint32_t dynb = smem_u32(dsm);
    const uint32_t base = (dynb + 1023u) & ~1023u;
    char* base_g = dsm + (base - dynb);
    const uint32_t Asm = base;            // 65536 bytes (4 chunks x 16KB)
    const uint32_t Bsm = base + 65536u;   // 49152 bytes (3 bufs x 16KB)

    const int tid = threadIdx.x, lane = tid & 31, wid = tid >> 5;
    const int warp_m = wid & 3, warp_n = wid >> 2;   // 4 x 2
    const int m0 = blockIdx.x << 7;      // 128 pixels per block
    const int b = m0 >> 10, n0 = m0 & 1023;

    // ---- stage A (128 rows x 256 fp16 = 64KB) + first two B slices ----
    const char* Ag = reinterpret_cast<const char*>(g_a);
    #pragma unroll
    for (int i = 0; i < 16; ++i) {
        int u = tid + (i << 8);          // 0..4095 16B units
        int s = u >> 10;                 // chunk 0..3
        int r = (u >> 3) & 127;          // row 0..127
        int c = u & 7;                   // 16B col 0..7
        uint32_t o = (uint32_t)(r << 7) + (uint32_t)(c << 4);
        cpa16(Asm + (s << 14) + (o ^ ((o >> 3) & 0x70)),
              Ag + (size_t)(m0 + r) * 512 + (s << 7) + (c << 4));
    }
    load_bslice(Bsm, 0, tid);
    asm volatile("cp.async.commit_group;");
    load_bslice(Bsm, 1, tid);
    asm volatile("cp.async.commit_group;");

    // per-lane ldmatrix address components
    uint32_t aoff[2], aswz[2];
    #pragma unroll
    for (int mt = 0; mt < 2; ++mt) {
        int rowA = warp_m * 32 + mt * 16 + (lane & 15);
        aoff[mt] = (uint32_t)rowA << 7;
        aswz[mt] = (uint32_t)(rowA & 7);
    }
    const uint32_t alc = (uint32_t)(lane >> 4);        // k-half select for A

    uint32_t boff[4], bswz[4];
    #pragma unroll
    for (int nt2 = 0; nt2 < 4; ++nt2) {
        int rowB = warp_n * 64 + nt2 * 16 + ((lane >> 4) << 3) + (lane & 7);
        boff[nt2] = (uint32_t)rowB << 7;
        bswz[nt2] = (uint32_t)(rowB & 7);
    }
    const uint32_t blc = (uint32_t)((lane >> 3) & 1);  // k-half select for B

    float acc[2][8][4];
    float t1v[4], t2v[4];
    int   t1i[4];
    #pragma unroll
    for (int s = 0; s < 4; ++s) { t1v[s] = -CUDART_INF_F; t2v[s] = -CUDART_INF_F; t1i[s] = 0; }

    for (int t = 0; t < 16; ++t) {
        const int pc = t >> 2, kb = t & 3;
        if (kb == 0) {
            #pragma unroll
            for (int i = 0; i < 2; ++i)
                #pragma unroll
                for (int j = 0; j < 8; ++j)
                    #pragma unroll
                    for (int q = 0; q < 4; ++q) acc[i][j][q] = 0.f;
        }
        // pipeline: wait(tile t ready) -> sync -> issue copy t+2 -> compute
        if (t < 15) asm volatile("cp.async.wait_group 1;");
        else        asm volatile("cp.async.wait_group 0;");
        __syncthreads();
        if (t + 2 < 16) {
            load_bslice(Bsm, t + 2, tid);
            asm volatile("cp.async.commit_group;");
        }

        const uint32_t Ab = Asm + ((uint32_t)kb << 14);
        const uint32_t Bb = Bsm + (uint32_t)(t % 3) * 16384u;

        #pragma unroll
        for (int k16 = 0; k16 < 4; ++k16) {
            uint32_t ra[2][4];
            #pragma unroll
            for (int mt = 0; mt < 2; ++mt) {
                uint32_t c16 = (uint32_t)(k16 << 1) + alc;
                LDSM_X4(ra[mt][0], ra[mt][1], ra[mt][2], ra[mt][3],
                        Ab + aoff[mt] + ((c16 ^ aswz[mt]) << 4));
            }
            #pragma unroll
            for (int nt2 = 0; nt2 < 4; ++nt2) {
                uint32_t c16 = (uint32_t)(k16 << 1) + blc;
                uint32_t rb[4];
                LDSM_X4(rb[0], rb[1], rb[2], rb[3],
                        Bb + boff[nt2] + ((c16 ^ bswz[nt2]) << 4));
                MMA16816(acc[0][2*nt2+0], ra[0], (rb + 0));
                MMA16816(acc[1][2*nt2+0], ra[1], (rb + 0));
                MMA16816(acc[0][2*nt2+1], ra[0], (rb + 2));
                MMA16816(acc[1][2*nt2+1], ra[1], (rb + 2));
            }
        }

        if (kb == 3) {     // fold chunk pc into running top-2
            #pragma unroll
            for (int mt = 0; mt < 2; ++mt)
                #pragma unroll
                for (int rh = 0; rh < 2; ++rh) {
                    int sl = mt * 2 + rh;
                    #pragma unroll
                    for (int nt = 0; nt < 8; ++nt)
                        #pragma unroll
                        for (int e = 0; e < 2; ++e) {
                            float v = acc[mt][nt][rh * 2 + e];
                            int col = (pc << 7) + (warp_n << 6) + (nt << 3)
                                    + ((lane & 3) << 1) + e;
                            if (v > t1v[sl]) { t2v[sl] = t1v[sl]; t1v[sl] = v; t1i[sl] = col; }
                            else if (v > t2v[sl]) t2v[sl] = v;
                        }
                }
        }
    }
    __syncthreads();

    // ---- cross-lane/warp reduction via smem (reuse A region) ----
    float* sv1 = reinterpret_cast<float*>(base_g);            // [128][8]
    int*   si1 = reinterpret_cast<int*>(base_g + 4096);
    float* sv2 = reinterpret_cast<float*>(base_g + 8192);
    int*   sIdx = reinterpret_cast<int*>(base_g + 12288);     // [128]
    #pragma unroll
    for (int mt = 0; mt < 2; ++mt)
        #pragma unroll
        for (int rh = 0; rh < 2; ++rh) {
            int sl = mt * 2 + rh;
            int row = warp_m * 32 + mt * 16 + rh * 8 + (lane >> 2);
            int cand = (warp_n << 2) + (lane & 3);
            sv1[row * 8 + cand] = t1v[sl];
            si1[row * 8 + cand] = t1i[sl];
            sv2[row * 8 + cand] = t2v[sl];
        }
    __syncthreads();

    if (tid < 128) {
        float v1 = -CUDART_INF_F, v2 = -CUDART_INF_F;
        int i1 = 0x7fffffff;
        #pragma unroll
        for (int c = 0; c < 8; ++c) {
            float cv1 = sv1[tid * 8 + c], cv2 = sv2[tid * 8 + c];
            int   ci1 = si1[tid * 8 + c];
            if (cv1 > v1 || (cv1 == v1 && ci1 < i1)) {
                v2 = fmaxf(v1, cv2); v1 = cv1; i1 = ci1;
            } else {
                v2 = fmaxf(v2, cv1);
            }
        }
        const int m = m0 + tid;
        sIdx[tid] = i1;
        if (out_size > 16777216LL) out[16777216 + m] = (float)i1;
        if (v1 - v2 < FIX_THRESH) {
            int pos = atomicAdd(&g_nfix, 1);
            g_fixlist[pos] = m;
        }
    }
    __syncthreads();

    // ---- fused gather: recon[b,c,h,w] = proto[idx][c], coalesced ----
    const int n4 = tid & 31;   // float4 col within 128-pixel tile
    const int ph = tid >> 5;   // channel phase 0..7
    const float* r0 = proto + (sIdx[(n4 << 2) + 0] << 8);
    const float* r1 = proto + (sIdx[(n4 << 2) + 1] << 8);
    const float* r2 = proto + (sIdx[(n4 << 2) + 2] << 8);
    const float* r3 = proto + (sIdx[(n4 << 2) + 3] << 8);
    float4* Og = reinterpret_cast<float4*>(out) + (b * 65536 + (n0 >> 2) + n4);
    #pragma unroll 4
    for (int c = ph; c < 256; c += 8)
        Og[c * 256] = make_float4(r0[c], r1[c], r2[c], r3[c]);
}

// ---------------------------------------------------------------------------
// Fixup: exact fp32 argmax for flagged pixels, 8 entries/block, 512 threads
// (one proto per thread). Patches recon rows of corrected pixels.
// ---------------------------------------------------------------------------
__global__ __launch_bounds__(512)
void fixup_kernel(const float* __restrict__ x, const float* __restrict__ proto,
                  float* __restrict__ out, long long out_size)
{
    __shared__ __align__(16) float xs[8][260];
    __shared__ float rbv[8][16];
    __shared__ int   rbi[8][16];
    __shared__ int   sfi[8];
    const int tid = threadIdx.x, lane = tid & 31, wid = tid >> 5;  // 16 warps
    const int nfix = g_nfix;

    for (int g0 = blockIdx.x * 8; g0 < nfix; g0 += gridDim.x * 8) {
        const int ne = min(8, nfix - g0);
        for (int i = tid; i < (ne << 8); i += 512) {
            int e = i >> 8, c = i & 255;
            int m = g_fixlist[g0 + e];
            xs[e][c] = x[(m >> 10) * 262144 + c * 1024 + (m & 1023)];
        }
        __syncthreads();

        const float4* pr = reinterpret_cast<const float4*>(g_pnf + (tid << 8));
        float acc[8];
        #pragma unroll
        for (int e = 0; e < 8; ++e) acc[e] = 0.f;
        #pragma unroll 4
        for (int c4 = 0; c4 < 64; ++c4) {
            float4 pv = pr[c4];
            #pragma unroll
            for (int e = 0; e < 8; ++e) {
                float4 xv = reinterpret_cast<const float4*>(xs[e])[c4];
                acc[e] = fmaf(pv.x, xv.x, acc[e]);
                acc[e] = fmaf(pv.y, xv.y, acc[e]);
                acc[e] = fmaf(pv.z, xv.z, acc[e]);
                acc[e] = fmaf(pv.w, xv.w, acc[e]);
            }
        }

        #pragma unroll
        for (int e = 0; e < 8; ++e) {
            float v = acc[e]; int ix = tid;
            #pragma unroll
            for (int s = 16; s >= 1; s >>= 1) {
                float ov = __shfl_xor_sync(0xffffffffu, v, s);
                int   oi = __shfl_xor_sync(0xffffffffu, ix, s);
                if (ov > v || (ov == v && oi < ix)) { v = ov; ix = oi; }
            }
            if (lane == 0) { rbv[e][wid] = v; rbi[e][wid] = ix; }
        }
        __syncthreads();

        if (tid < ne) {
            float fv = rbv[tid][0]; int fi = rbi[tid][0];
            #pragma unroll
            for (int w = 1; w < 16; ++w)
                if (rbv[tid][w] > fv || (rbv[tid][w] == fv && rbi[tid][w] < fi)) {
                    fv = rbv[tid][w]; fi = rbi[tid][w];
                }
            sfi[tid] = fi;
            const int m = g_fixlist[g0 + tid];
            if (out_size > 16777216LL) out[16777216 + m] = (float)fi;
        }
        __syncthreads();

        const int c  = tid & 255;
        const int eh = tid >> 8;
        for (int e = eh; e < ne; e += 2) {
            const int m = g_fixlist[g0 + e];
            out[(m >> 10) * 262144 + c * 1024 + (m & 1023)] = proto[(sfi[e] << 8) + c];
        }
        __syncthreads();
    }
}

// ---------------------------------------------------------------------------
extern "C" void kernel_launch(void* const* d_in, const int* in_sizes, int n_in,
                              void* d_out, int out_size)
{
    const float* x     = (const float*)d_in[0];
    const float* proto = (const float*)d_in[1];
    if (n_in >= 2 && in_sizes[0] == 512 * 256 && in_sizes[1] != 512 * 256) {
        proto = (const float*)d_in[0];
        x     = (const float*)d_in[1];
    }
    float* out = (float*)d_out;

    proto_prep_kernel<<<512, 256>>>(proto);
    xsplit_kernel<<<dim3(4, 32, 64), 256>>>(x);

    cudaFuncSetAttribute(protomatch_mma,
                         cudaFuncAttributeMaxDynamicSharedMemorySize, 115712);
    protomatch_mma<<<512, 256, 115712>>>(proto, out, (long long)out_size);

    fixup_kernel<<<256, 512>>>(x, proto, out, (long long)out_size);
}